// round 1
// baseline (speedup 1.0000x reference)
#include <cuda_runtime.h>
#include <math.h>

// Problem constants (fixed by the dataset)
#define N_NODES 20000
#define N_GRAPH 64
#define NH 4          // heads
#define NC 64         // channels per head / output channels
#define NFIN 128      // input features
#define NHC 256       // NH * NC
#define E_RAW 320000
#define E_TOT (E_RAW + N_NODES)   // + self loops
#define BN_EPS 1e-5f

// ---------------- scratch (device globals; no allocations allowed) ----------
static __device__ float g_h1[N_NODES * NHC];    // projected features [N,H,C]
static __device__ float g_skip[N_NODES * NC];   // x @ Wskip
static __device__ float g_es[N_NODES * NH];
static __device__ float g_ed[N_NODES * NH];
static __device__ float g_m[N_NODES * NH];      // segment max
static __device__ float g_s[N_NODES * NH];      // segment sum of exp
static __device__ float g_p[E_TOT * NH];        // per-edge e then p
static __device__ float g_acc[N_NODES * NC];    // GAT output accumulator (head-mean folded)
static __device__ float g_hmid[N_NODES * NC];   // layer-1 output h
static __device__ float g_sums[NC];
static __device__ float g_sumsq[NC];
static __device__ float g_scale[NC];
static __device__ float g_shift[NC];
static __device__ float g_psum[N_GRAPH * NC];
static __device__ float g_pcnt[N_GRAPH];

// ---------------- helpers ---------------------------------------------------
__device__ __forceinline__ void atomicMaxF(float* addr, float v) {
    // ordered-bit trick; correct with -inf initialization
    if (v >= 0.f) atomicMax((int*)addr, __float_as_int(v));
    else          atomicMin((unsigned int*)addr, __float_as_uint(v));
}

__device__ __forceinline__ float gelu_exact(float x) {
    return 0.5f * x * (1.f + erff(x * 0.70710678118654752440f));
}

// ---------------- resets -----------------------------------------------------
__global__ void reset_layer_kernel() {
    int i = blockIdx.x * blockDim.x + threadIdx.x;
    if (i < N_NODES * NH) { g_m[i] = __int_as_float(0xff800000); g_s[i] = 0.f; }
    if (i < N_NODES * NC) g_acc[i] = 0.f;
    if (i < NC) { g_sums[i] = 0.f; g_sumsq[i] = 0.f; }
}

__global__ void reset_pool_kernel() {
    int i = blockIdx.x * blockDim.x + threadIdx.x;
    if (i < N_GRAPH * NC) g_psum[i] = 0.f;
    if (i < N_GRAPH) g_pcnt[i] = 0.f;
}

// ---------------- GEMM: C[n,ncols] = A[n,K] @ B[K,ncols]  (fp32, smem-tiled) --
__global__ void __launch_bounds__(256) gemm_kernel(
    const float* __restrict__ A, const float* __restrict__ B, float* __restrict__ Cout,
    int n, int K, int ncols)
{
    __shared__ float As[64][65];
    __shared__ float Bs[64][64];
    const int tid = threadIdx.x;
    const int row0 = blockIdx.x * 64, col0 = blockIdx.y * 64;
    const int tr = tid >> 4, tc = tid & 15;
    float acc[4][4];
#pragma unroll
    for (int i = 0; i < 4; i++)
#pragma unroll
        for (int j = 0; j < 4; j++) acc[i][j] = 0.f;

    for (int kc = 0; kc < K; kc += 64) {
        for (int i = tid; i < 64 * 64; i += 256) {
            int r = i >> 6, k = i & 63;
            int gr = row0 + r;
            As[r][k] = (gr < n) ? A[gr * K + kc + k] : 0.f;
            Bs[r][k] = B[(kc + r) * ncols + col0 + k];
        }
        __syncthreads();
#pragma unroll
        for (int k = 0; k < 64; k++) {
            float4 b = *(const float4*)&Bs[k][tc * 4];
            float a0 = As[tr * 4 + 0][k];
            float a1 = As[tr * 4 + 1][k];
            float a2 = As[tr * 4 + 2][k];
            float a3 = As[tr * 4 + 3][k];
            acc[0][0] += a0 * b.x; acc[0][1] += a0 * b.y; acc[0][2] += a0 * b.z; acc[0][3] += a0 * b.w;
            acc[1][0] += a1 * b.x; acc[1][1] += a1 * b.y; acc[1][2] += a1 * b.z; acc[1][3] += a1 * b.w;
            acc[2][0] += a2 * b.x; acc[2][1] += a2 * b.y; acc[2][2] += a2 * b.z; acc[2][3] += a2 * b.w;
            acc[3][0] += a3 * b.x; acc[3][1] += a3 * b.y; acc[3][2] += a3 * b.z; acc[3][3] += a3 * b.w;
        }
        __syncthreads();
    }
#pragma unroll
    for (int i = 0; i < 4; i++) {
        int gr = row0 + tr * 4 + i;
        if (gr < n) {
            float4 v = make_float4(acc[i][0], acc[i][1], acc[i][2], acc[i][3]);
            *(float4*)&Cout[gr * ncols + col0 + tc * 4] = v;
        }
    }
}

// ---------------- attention coefficients es/ed (warp per node) ---------------
__global__ void attn_kernel(const float* __restrict__ a_src, const float* __restrict__ a_dst, int n) {
    int w = (blockIdx.x * blockDim.x + threadIdx.x) >> 5;
    int lane = threadIdx.x & 31;
    if (w >= n) return;
    const float* hr = g_h1 + (size_t)w * NHC;
    int base = lane * 8;   // 8 consecutive elems; stays within one head (64 | 8)
    float ps = 0.f, pd = 0.f;
#pragma unroll
    for (int j = 0; j < 8; j++) {
        float v = hr[base + j];
        ps += v * a_src[base + j];
        pd += v * a_dst[base + j];
    }
#pragma unroll
    for (int off = 4; off > 0; off >>= 1) {
        ps += __shfl_down_sync(0xffffffffu, ps, off);
        pd += __shfl_down_sync(0xffffffffu, pd, off);
    }
    if ((lane & 7) == 0) {
        int h = lane >> 3;
        g_es[w * NH + h] = ps;
        g_ed[w * NH + h] = pd;
    }
}

// ---------------- edge pass 1: leaky-relu logit + segment max ----------------
__global__ void edge_pass1_kernel(const int* __restrict__ ei, int E, int etot) {
    int e = blockIdx.x * blockDim.x + threadIdx.x;
    if (e >= etot) return;
    int s, d;
    if (e < E) { s = ei[e]; d = ei[E + e]; } else { s = e - E; d = s; }
    float4 a = *(const float4*)&g_es[s * 4];
    float4 b = *(const float4*)&g_ed[d * 4];
    float4 v;
    v.x = a.x + b.x; v.y = a.y + b.y; v.z = a.z + b.z; v.w = a.w + b.w;
    v.x = v.x > 0.f ? v.x : 0.2f * v.x;
    v.y = v.y > 0.f ? v.y : 0.2f * v.y;
    v.z = v.z > 0.f ? v.z : 0.2f * v.z;
    v.w = v.w > 0.f ? v.w : 0.2f * v.w;
    *(float4*)&g_p[e * 4] = v;
    atomicMaxF(&g_m[d * 4 + 0], v.x);
    atomicMaxF(&g_m[d * 4 + 1], v.y);
    atomicMaxF(&g_m[d * 4 + 2], v.z);
    atomicMaxF(&g_m[d * 4 + 3], v.w);
}

// ---------------- edge pass 2: p = exp(e - m[dst]); segment sum --------------
__global__ void edge_pass2_kernel(const int* __restrict__ ei, int E, int etot) {
    int e = blockIdx.x * blockDim.x + threadIdx.x;
    if (e >= etot) return;
    int d = (e < E) ? ei[E + e] : (e - E);
    float4 v = *(const float4*)&g_p[e * 4];
    float4 m = *(const float4*)&g_m[d * 4];
    v.x = expf(v.x - m.x);
    v.y = expf(v.y - m.y);
    v.z = expf(v.z - m.z);
    v.w = expf(v.w - m.w);
    *(float4*)&g_p[e * 4] = v;
    atomicAdd(&g_s[d * 4 + 0], v.x);
    atomicAdd(&g_s[d * 4 + 1], v.y);
    atomicAdd(&g_s[d * 4 + 2], v.z);
    atomicAdd(&g_s[d * 4 + 3], v.w);
}

// ---- edge pass 3: scatter alpha-weighted features, head-mean folded (x0.25) -
__global__ void edge_pass3_kernel(const int* __restrict__ ei, int E, int etot) {
    int w = (blockIdx.x * blockDim.x + threadIdx.x) >> 5;
    int lane = threadIdx.x & 31;
    if (w >= etot) return;
    int s, d;
    if (w < E) { s = ei[w]; d = ei[E + w]; } else { s = w - E; d = s; }
    float4 p = *(const float4*)&g_p[w * 4];
    float4 sv = *(const float4*)&g_s[d * 4];
    float a0 = p.x / (sv.x + 1e-16f) * 0.25f;
    float a1 = p.y / (sv.y + 1e-16f) * 0.25f;
    float a2 = p.z / (sv.z + 1e-16f) * 0.25f;
    float a3 = p.w / (sv.w + 1e-16f) * 0.25f;
    const float* hr = g_h1 + (size_t)s * NHC;
    float v0 = a0 * hr[lane]       + a1 * hr[64 + lane]  + a2 * hr[128 + lane] + a3 * hr[192 + lane];
    float v1 = a0 * hr[32 + lane]  + a1 * hr[96 + lane]  + a2 * hr[160 + lane] + a3 * hr[224 + lane];
    atomicAdd(&g_acc[d * NC + lane], v0);
    atomicAdd(&g_acc[d * NC + 32 + lane], v1);
}

// ---------------- BatchNorm statistics over g_acc ----------------------------
__global__ void bn_stats_kernel(int n) {
    __shared__ float ssum[256], ssq[256];
    int c = threadIdx.x & 63, rq = threadIdx.x >> 6;
    int r0 = blockIdx.x * 128;
    int rend = r0 + 128; if (rend > n) rend = n;
    float s = 0.f, q = 0.f;
    for (int r = r0 + rq; r < rend; r += 4) {
        float v = g_acc[r * NC + c];
        s += v; q += v * v;
    }
    ssum[threadIdx.x] = s; ssq[threadIdx.x] = q;
    __syncthreads();
    if (rq == 0) {
        s = ssum[c] + ssum[c + 64] + ssum[c + 128] + ssum[c + 192];
        q = ssq[c] + ssq[c + 64] + ssq[c + 128] + ssq[c + 192];
        atomicAdd(&g_sums[c], s);
        atomicAdd(&g_sumsq[c], q);
    }
}

// NOTE: GAT bias b1/b2 cancels exactly inside BatchNorm (additive constant),
// so it is intentionally never applied.
__global__ void bn_finalize_kernel(const float* __restrict__ gamma,
                                   const float* __restrict__ beta, int n) {
    int c = threadIdx.x;
    if (c >= NC) return;
    float inv = 1.f / (float)n;
    float mu = g_sums[c] * inv;
    float var = g_sumsq[c] * inv - mu * mu;
    float sc = gamma[c] * rsqrtf(var + BN_EPS);
    g_scale[c] = sc;
    g_shift[c] = beta[c] - mu * sc;
}

// ---------------- fused epilogue 1: h = gelu(BN(gat1) + x@Wskip + bskip) -----
__global__ void fuse1_kernel(const float* __restrict__ bskip, int total) {
    int i = blockIdx.x * blockDim.x + threadIdx.x;
    if (i >= total) return;
    int c = i & 63;
    float x = g_acc[i] * g_scale[c] + g_shift[c] + g_skip[i] + bskip[c];
    g_hmid[i] = gelu_exact(x);
}

// ------- fused epilogue 2 + pool: h2 = gelu(BN(gat2)+h); scatter to graphs ---
__global__ void fuse2_pool_kernel(const int* __restrict__ batch, int total) {
    int i = blockIdx.x * blockDim.x + threadIdx.x;
    if (i >= total) return;
    int c = i & 63;
    int node = i >> 6;
    float x = g_acc[i] * g_scale[c] + g_shift[c] + g_hmid[i];
    float y = gelu_exact(x);
    int b = batch[node];
    atomicAdd(&g_psum[b * NC + c], y);
    if (c == 0) atomicAdd(&g_pcnt[b], 1.f);
}

__global__ void pool_finalize_kernel(float* __restrict__ out) {
    int i = blockIdx.x * blockDim.x + threadIdx.x;
    if (i >= N_GRAPH * NC) return;
    out[i] = g_psum[i] / fmaxf(g_pcnt[i >> 6], 1.f);
}

// ---------------- launch -----------------------------------------------------
extern "C" void kernel_launch(void* const* d_in, const int* in_sizes, int n_in,
                              void* d_out, int out_size) {
    const float* x      = (const float*)d_in[0];
    const float* W1     = (const float*)d_in[1];
    const float* a_src1 = (const float*)d_in[2];
    const float* a_dst1 = (const float*)d_in[3];
    // d_in[4] = b1 : cancels in BN
    const float* Wskip  = (const float*)d_in[5];
    const float* bskip  = (const float*)d_in[6];
    const float* g1     = (const float*)d_in[7];
    const float* be1    = (const float*)d_in[8];
    const float* W2     = (const float*)d_in[9];
    const float* a_src2 = (const float*)d_in[10];
    const float* a_dst2 = (const float*)d_in[11];
    // d_in[12] = b2 : cancels in BN
    const float* g2     = (const float*)d_in[13];
    const float* be2    = (const float*)d_in[14];
    const int*   ei     = (const int*)d_in[15];
    const int*   batch  = (const int*)d_in[16];
    float* out = (float*)d_out;

    int n = in_sizes[0] / NFIN;        // 20000
    int E = in_sizes[15] / 2;          // 320000
    int etot = E + n;

    float *p_h1, *p_skip, *p_hmid;
    cudaGetSymbolAddress((void**)&p_h1, g_h1);
    cudaGetSymbolAddress((void**)&p_skip, g_skip);
    cudaGetSymbolAddress((void**)&p_hmid, g_hmid);

    int rb = (N_NODES * NC + 255) / 256;
    int eb = (etot + 255) / 256;
    int wb = (etot + 7) / 8;           // warp per edge, 8 warps/block
    int nb = (n + 7) / 8;              // warp per node
    int fb = (n * NC + 255) / 256;

    // ---------------- layer 1
    reset_layer_kernel<<<rb, 256>>>();
    gemm_kernel<<<dim3((n + 63) / 64, NHC / 64), 256>>>(x, W1, p_h1, n, NFIN, NHC);
    gemm_kernel<<<dim3((n + 63) / 64, 1), 256>>>(x, Wskip, p_skip, n, NFIN, NC);
    attn_kernel<<<nb, 256>>>(a_src1, a_dst1, n);
    edge_pass1_kernel<<<eb, 256>>>(ei, E, etot);
    edge_pass2_kernel<<<eb, 256>>>(ei, E, etot);
    edge_pass3_kernel<<<wb, 256>>>(ei, E, etot);
    bn_stats_kernel<<<(n + 127) / 128, 256>>>(n);
    bn_finalize_kernel<<<1, 64>>>(g1, be1, n);
    fuse1_kernel<<<fb, 256>>>(bskip, n * NC);

    // ---------------- layer 2
    reset_layer_kernel<<<rb, 256>>>();
    gemm_kernel<<<dim3((n + 63) / 64, NHC / 64), 256>>>(p_hmid, W2, p_h1, n, NC, NHC);
    attn_kernel<<<nb, 256>>>(a_src2, a_dst2, n);
    edge_pass1_kernel<<<eb, 256>>>(ei, E, etot);
    edge_pass2_kernel<<<eb, 256>>>(ei, E, etot);
    edge_pass3_kernel<<<wb, 256>>>(ei, E, etot);
    bn_stats_kernel<<<(n + 127) / 128, 256>>>(n);
    bn_finalize_kernel<<<1, 64>>>(g2, be2, n);

    // ---------------- pool
    reset_pool_kernel<<<(N_GRAPH * NC + 255) / 256, 256>>>();
    fuse2_pool_kernel<<<fb, 256>>>(batch, n * NC);
    pool_finalize_kernel<<<(N_GRAPH * NC + 255) / 256, 256>>>(out);
}

// round 2
// speedup vs baseline: 1.3050x; 1.3050x over previous
#include <cuda_runtime.h>
#include <math.h>

#define N_NODES 20000
#define N_GRAPH 64
#define NH 4
#define NC 64
#define NFIN 128
#define NHC 256
#define E_RAW 320000
#define E_TOT (E_RAW + N_NODES)
#define BN_EPS 1e-5f

// ---------------- scratch (device globals) ----------------
static __device__ float g_h1[N_NODES * NHC];
static __device__ float g_skip[N_NODES * NC];
static __device__ float g_es[N_NODES * NH];
static __device__ float g_ed[N_NODES * NH];
static __device__ float g_p[E_TOT * NH];
static __device__ float g_acc[N_NODES * NC];
static __device__ float g_hmid[N_NODES * NC];
static __device__ float g_sums[NC], g_sumsq[NC], g_scale[NC], g_shift[NC];
static __device__ int   g_cnt[N_NODES];
static __device__ int   g_rowptr[N_NODES + 1];
static __device__ int   g_cursor[N_NODES];
static __device__ int   g_csrc[E_TOT];
static __device__ int   g_cdst[E_TOT];

__device__ __forceinline__ float gelu_exact(float x) {
    return 0.5f * x * (1.f + erff(x * 0.70710678118654752440f));
}

// ================= CSR construction =================
__global__ void zero_cnt_kernel(int n) {
    int i = blockIdx.x * blockDim.x + threadIdx.x;
    if (i < n) g_cnt[i] = 0;
}

__global__ void hist_kernel(const int* __restrict__ ei, int E, int etot) {
    int e = blockIdx.x * blockDim.x + threadIdx.x;
    if (e >= etot) return;
    int d = (e < E) ? ei[E + e] : (e - E);
    atomicAdd(&g_cnt[d], 1);
}

// single-block exclusive scan of g_cnt -> g_rowptr, g_cursor
__global__ void __launch_bounds__(1024) scan_kernel(int n) {
    const int PER = 20;
    int t = threadIdx.x;
    int base = t * PER;
    int v[PER];
    int s = 0;
#pragma unroll
    for (int i = 0; i < PER; i++) {
        v[i] = (base + i < n) ? g_cnt[base + i] : 0;
        s += v[i];
    }
    __shared__ int sh[1024];
    sh[t] = s;
    __syncthreads();
    for (int off = 1; off < 1024; off <<= 1) {
        int x = (t >= off) ? sh[t - off] : 0;
        __syncthreads();
        sh[t] += x;
        __syncthreads();
    }
    int run = sh[t] - s;  // exclusive prefix
#pragma unroll
    for (int i = 0; i < PER; i++) {
        if (base + i < n) {
            g_rowptr[base + i] = run;
            g_cursor[base + i] = run;
        }
        run += v[i];
    }
    if (t == 1023) g_rowptr[n] = sh[1023];
}

__global__ void scatter_kernel(const int* __restrict__ ei, int E, int etot) {
    int e = blockIdx.x * blockDim.x + threadIdx.x;
    if (e >= etot) return;
    int s, d;
    if (e < E) { s = ei[e]; d = ei[E + e]; } else { s = e - E; d = s; }
    int pos = atomicAdd(&g_cursor[d], 1);
    g_csrc[pos] = s;
    g_cdst[pos] = d;
}

// ================= GEMM: C[n,ncols] = A[n,K]@B[K,ncols], tile 128x64xK32 ====
// If ATTN: also emits g_es/g_ed for head = blockIdx.y (requires ncols=256,
// tileN=64 so each block covers exactly one head).
template <bool ATTN>
__global__ void __launch_bounds__(256) gemm_kernel(
    const float* __restrict__ A, const float* __restrict__ B,
    float* __restrict__ C, int n, int K, int ncols,
    const float* __restrict__ asrc, const float* __restrict__ adst)
{
    __shared__ float As[32 * 132];  // As[k][m], stride 132
    __shared__ float Bs[32 * 64];   // Bs[k][c]
    const int tid = threadIdx.x;
    const int tx = tid & 15, ty = tid >> 4;
    const int bm = blockIdx.x * 128, bn = blockIdx.y * 64;

    float acc[8][4];
#pragma unroll
    for (int r = 0; r < 8; r++)
#pragma unroll
        for (int j = 0; j < 4; j++) acc[r][j] = 0.f;

    const int lm = tid >> 1;            // row this thread loads (0..127)
    const int kh = (tid & 1) * 16;      // k half

    for (int k0 = 0; k0 < K; k0 += 32) {
        // load A tile (transposed into As[k][m])
        {
            int row = bm + lm;
            const float* Arow = A + (size_t)row * K + k0 + kh;
#pragma unroll
            for (int u = 0; u < 4; u++) {
                float4 a = (row < n) ? *(const float4*)(Arow + 4 * u)
                                     : make_float4(0.f, 0.f, 0.f, 0.f);
                As[(kh + 4 * u + 0) * 132 + lm] = a.x;
                As[(kh + 4 * u + 1) * 132 + lm] = a.y;
                As[(kh + 4 * u + 2) * 132 + lm] = a.z;
                As[(kh + 4 * u + 3) * 132 + lm] = a.w;
            }
        }
        // load B tile
        {
            int kr = tid >> 3, c = (tid & 7) * 8;
            const float* Brow = B + (size_t)(k0 + kr) * ncols + bn + c;
            *(float4*)&Bs[kr * 64 + c]     = *(const float4*)(Brow);
            *(float4*)&Bs[kr * 64 + c + 4] = *(const float4*)(Brow + 4);
        }
        __syncthreads();
#pragma unroll
        for (int k = 0; k < 32; k++) {
            float4 a0 = *(const float4*)&As[k * 132 + ty * 8];
            float4 a1 = *(const float4*)&As[k * 132 + ty * 8 + 4];
            float4 b  = *(const float4*)&Bs[k * 64 + tx * 4];
            acc[0][0] += a0.x * b.x; acc[0][1] += a0.x * b.y; acc[0][2] += a0.x * b.z; acc[0][3] += a0.x * b.w;
            acc[1][0] += a0.y * b.x; acc[1][1] += a0.y * b.y; acc[1][2] += a0.y * b.z; acc[1][3] += a0.y * b.w;
            acc[2][0] += a0.z * b.x; acc[2][1] += a0.z * b.y; acc[2][2] += a0.z * b.z; acc[2][3] += a0.z * b.w;
            acc[3][0] += a0.w * b.x; acc[3][1] += a0.w * b.y; acc[3][2] += a0.w * b.z; acc[3][3] += a0.w * b.w;
            acc[4][0] += a1.x * b.x; acc[4][1] += a1.x * b.y; acc[4][2] += a1.x * b.z; acc[4][3] += a1.x * b.w;
            acc[5][0] += a1.y * b.x; acc[5][1] += a1.y * b.y; acc[5][2] += a1.y * b.z; acc[5][3] += a1.y * b.w;
            acc[6][0] += a1.z * b.x; acc[6][1] += a1.z * b.y; acc[6][2] += a1.z * b.z; acc[6][3] += a1.z * b.w;
            acc[7][0] += a1.w * b.x; acc[7][1] += a1.w * b.y; acc[7][2] += a1.w * b.z; acc[7][3] += a1.w * b.w;
        }
        __syncthreads();
    }
    // store C
#pragma unroll
    for (int r = 0; r < 8; r++) {
        int row = bm + ty * 8 + r;
        if (row < n) {
            float4 v = make_float4(acc[r][0], acc[r][1], acc[r][2], acc[r][3]);
            *(float4*)&C[(size_t)row * ncols + bn + tx * 4] = v;
        }
    }
    if (ATTN) {
        // per-row dot with a_src / a_dst (this block's 64 cols = head blockIdx.y)
        float avs[4], avd[4];
#pragma unroll
        for (int j = 0; j < 4; j++) {
            avs[j] = asrc[bn + tx * 4 + j];
            avd[j] = adst[bn + tx * 4 + j];
        }
        float* Ses = As;          // 128*16
        float* Sed = As + 2048;   // 128*16
#pragma unroll
        for (int r = 0; r < 8; r++) {
            float ps = acc[r][0] * avs[0] + acc[r][1] * avs[1] + acc[r][2] * avs[2] + acc[r][3] * avs[3];
            float pd = acc[r][0] * avd[0] + acc[r][1] * avd[1] + acc[r][2] * avd[2] + acc[r][3] * avd[3];
            Ses[(ty * 8 + r) * 16 + tx] = ps;
            Sed[(ty * 8 + r) * 16 + tx] = pd;
        }
        __syncthreads();
        if (tid < 128) {
            int row = bm + tid;
            if (row < n) {
                float s = 0.f, d2 = 0.f;
#pragma unroll
                for (int j = 0; j < 16; j++) {
                    s  += Ses[tid * 16 + j];
                    d2 += Sed[tid * 16 + j];
                }
                g_es[row * 4 + blockIdx.y] = s;
                g_ed[row * 4 + blockIdx.y] = d2;
            }
        }
    }
}

// ============ pass A: p = exp(leakyrelu(es[src]+ed[dst])) per CSR pos =======
__global__ void passA_kernel(int etot) {
    int pos = blockIdx.x * blockDim.x + threadIdx.x;
    if (pos >= etot) return;
    int s = g_csrc[pos], d = g_cdst[pos];
    float4 a = *(const float4*)&g_es[s * 4];
    float4 b = *(const float4*)&g_ed[d * 4];
    float4 v;
    v.x = a.x + b.x; v.y = a.y + b.y; v.z = a.z + b.z; v.w = a.w + b.w;
    v.x = v.x > 0.f ? v.x : 0.2f * v.x;
    v.y = v.y > 0.f ? v.y : 0.2f * v.y;
    v.z = v.z > 0.f ? v.z : 0.2f * v.z;
    v.w = v.w > 0.f ? v.w : 0.2f * v.w;
    v.x = __expf(v.x) ; // fast exp: |e| small, accuracy ~1e-6 rel
    v.y = __expf(v.y);
    v.z = __expf(v.z);
    v.w = __expf(v.w);
    *(float4*)&g_p[pos * 4] = v;
}

// ===== pass B: warp per dst; gather p*h[src], fold softmax norm + head mean =
__global__ void aggregate_kernel(int n) {
    int w = (blockIdx.x * blockDim.x + threadIdx.x) >> 5;
    int lane = threadIdx.x & 31;
    if (w >= n) return;
    int beg = g_rowptr[w], end = g_rowptr[w + 1];
    float s0 = 0.f, s1 = 0.f, s2 = 0.f, s3 = 0.f;
    float a00 = 0.f, a01 = 0.f, a10 = 0.f, a11 = 0.f;
    float a20 = 0.f, a21 = 0.f, a30 = 0.f, a31 = 0.f;
#pragma unroll 2
    for (int pos = beg; pos < end; pos++) {
        float4 p = *(const float4*)&g_p[pos * 4];        // uniform broadcast
        int src = g_csrc[pos];                            // uniform broadcast
        const float2* hr2 = (const float2*)(g_h1 + (size_t)src * NHC);
        float2 v0 = hr2[lane];         // head 0, channels 2l,2l+1
        float2 v1 = hr2[32 + lane];    // head 1
        float2 v2 = hr2[64 + lane];    // head 2
        float2 v3 = hr2[96 + lane];    // head 3
        a00 += p.x * v0.x; a01 += p.x * v0.y;
        a10 += p.y * v1.x; a11 += p.y * v1.y;
        a20 += p.z * v2.x; a21 += p.z * v2.y;
        a30 += p.w * v3.x; a31 += p.w * v3.y;
        s0 += p.x; s1 += p.y; s2 += p.z; s3 += p.w;
    }
    float i0 = 0.25f / (s0 + 1e-16f);
    float i1 = 0.25f / (s1 + 1e-16f);
    float i2 = 0.25f / (s2 + 1e-16f);
    float i3 = 0.25f / (s3 + 1e-16f);
    float2 o;
    o.x = a00 * i0 + a10 * i1 + a20 * i2 + a30 * i3;
    o.y = a01 * i0 + a11 * i1 + a21 * i2 + a31 * i3;
    *(float2*)&g_acc[w * NC + 2 * lane] = o;
}

// ================= BatchNorm =================
__global__ void zero_stats_kernel() {
    int c = threadIdx.x;
    if (c < NC) { g_sums[c] = 0.f; g_sumsq[c] = 0.f; }
}

__global__ void bn_stats_kernel(int n) {
    __shared__ float ssum[256], ssq[256];
    int c = threadIdx.x & 63, rq = threadIdx.x >> 6;
    int r0 = blockIdx.x * 128;
    int rend = r0 + 128; if (rend > n) rend = n;
    float s = 0.f, q = 0.f;
    for (int r = r0 + rq; r < rend; r += 4) {
        float v = g_acc[r * NC + c];
        s += v; q += v * v;
    }
    ssum[threadIdx.x] = s; ssq[threadIdx.x] = q;
    __syncthreads();
    if (rq == 0) {
        s = ssum[c] + ssum[c + 64] + ssum[c + 128] + ssum[c + 192];
        q = ssq[c] + ssq[c + 64] + ssq[c + 128] + ssq[c + 192];
        atomicAdd(&g_sums[c], s);
        atomicAdd(&g_sumsq[c], q);
    }
}

// GAT bias b1/b2 cancels inside BatchNorm (additive constant) -> never applied.
__global__ void bn_finalize_kernel(const float* __restrict__ gamma,
                                   const float* __restrict__ beta, int n) {
    int c = threadIdx.x;
    if (c >= NC) return;
    float inv = 1.f / (float)n;
    float mu = g_sums[c] * inv;
    float var = g_sumsq[c] * inv - mu * mu;
    float sc = gamma[c] * rsqrtf(var + BN_EPS);
    g_scale[c] = sc;
    g_shift[c] = beta[c] - mu * sc;
}

// ======= fused epilogue 1: h = gelu(BN(gat1) + skip + bskip) =======
__global__ void fuse1_kernel(const float* __restrict__ bskip, int total) {
    int i = blockIdx.x * blockDim.x + threadIdx.x;
    if (i >= total) return;
    int c = i & 63;
    float x = g_acc[i] * g_scale[c] + g_shift[c] + g_skip[i] + bskip[c];
    g_hmid[i] = gelu_exact(x);
}

// ======= fused epilogue 2 + pool: block per graph, no atomics =======
__device__ __forceinline__ int lower_bound_dev(const int* arr, int n, int target) {
    int lo = 0, hi = n;
    while (lo < hi) {
        int mid = (lo + hi) >> 1;
        if (arr[mid] < target) lo = mid + 1; else hi = mid;
    }
    return lo;
}

__global__ void fuse2_pool_kernel(const int* __restrict__ batch,
                                  float* __restrict__ out, int n) {
    int g = blockIdx.x;
    __shared__ int bounds[2];
    if (threadIdx.x < 2)
        bounds[threadIdx.x] = lower_bound_dev(batch, n, g + threadIdx.x);
    __syncthreads();
    int lo = bounds[0], hi = bounds[1];
    int c = threadIdx.x & 63, rq = threadIdx.x >> 6;
    float s = 0.f;
    for (int node = lo + rq; node < hi; node += 4) {
        float x = g_acc[node * NC + c] * g_scale[c] + g_shift[c] + g_hmid[node * NC + c];
        s += gelu_exact(x);
    }
    __shared__ float red[256];
    red[threadIdx.x] = s;
    __syncthreads();
    if (threadIdx.x < 64) {
        float tot = red[c] + red[c + 64] + red[c + 128] + red[c + 192];
        out[g * NC + c] = tot / fmaxf((float)(hi - lo), 1.f);
    }
}

// ================= launch =================
extern "C" void kernel_launch(void* const* d_in, const int* in_sizes, int n_in,
                              void* d_out, int out_size) {
    const float* x      = (const float*)d_in[0];
    const float* W1     = (const float*)d_in[1];
    const float* a_src1 = (const float*)d_in[2];
    const float* a_dst1 = (const float*)d_in[3];
    const float* Wskip  = (const float*)d_in[5];
    const float* bskip  = (const float*)d_in[6];
    const float* g1     = (const float*)d_in[7];
    const float* be1    = (const float*)d_in[8];
    const float* W2     = (const float*)d_in[9];
    const float* a_src2 = (const float*)d_in[10];
    const float* a_dst2 = (const float*)d_in[11];
    const float* g2     = (const float*)d_in[13];
    const float* be2    = (const float*)d_in[14];
    const int*   ei     = (const int*)d_in[15];
    const int*   batch  = (const int*)d_in[16];
    float* out = (float*)d_out;

    int n = in_sizes[0] / NFIN;    // 20000
    int E = in_sizes[15] / 2;      // 320000
    int etot = E + n;

    float *p_h1, *p_skip, *p_hmid;
    cudaGetSymbolAddress((void**)&p_h1, g_h1);
    cudaGetSymbolAddress((void**)&p_skip, g_skip);
    cudaGetSymbolAddress((void**)&p_hmid, g_hmid);

    int eb = (etot + 255) / 256;
    int gx = (n + 127) / 128;
    int fb = (n * NC + 255) / 256;
    int ab = (n * 32 + 255) / 256;     // warp per node

    // CSR (shared by both layers)
    zero_cnt_kernel<<<(n + 255) / 256, 256>>>(n);
    hist_kernel<<<eb, 256>>>(ei, E, etot);
    scan_kernel<<<1, 1024>>>(n);
    scatter_kernel<<<eb, 256>>>(ei, E, etot);

    // ---- layer 1
    gemm_kernel<true><<<dim3(gx, 4), 256>>>(x, W1, p_h1, n, NFIN, NHC, a_src1, a_dst1);
    gemm_kernel<false><<<dim3(gx, 1), 256>>>(x, Wskip, p_skip, n, NFIN, NC, nullptr, nullptr);
    passA_kernel<<<eb, 256>>>(etot);
    aggregate_kernel<<<ab, 256>>>(n);
    zero_stats_kernel<<<1, 64>>>();
    bn_stats_kernel<<<(n + 127) / 128, 256>>>(n);
    bn_finalize_kernel<<<1, 64>>>(g1, be1, n);
    fuse1_kernel<<<fb, 256>>>(bskip, n * NC);

    // ---- layer 2
    gemm_kernel<true><<<dim3(gx, 4), 256>>>(p_hmid, W2, p_h1, n, NC, NHC, a_src2, a_dst2);
    passA_kernel<<<eb, 256>>>(etot);
    aggregate_kernel<<<ab, 256>>>(n);
    zero_stats_kernel<<<1, 64>>>();
    bn_stats_kernel<<<(n + 127) / 128, 256>>>(n);
    bn_finalize_kernel<<<1, 64>>>(g2, be2, n);

    // ---- fused epilogue 2 + mean pool
    fuse2_pool_kernel<<<N_GRAPH, 256>>>(batch, out, n);
}

// round 3
// speedup vs baseline: 1.4019x; 1.0742x over previous
#include <cuda_runtime.h>
#include <cuda_fp16.h>
#include <math.h>

#define N_NODES 20000
#define N_GRAPH 64
#define NH 4
#define NC 64
#define NFIN 128
#define NHC 256
#define E_RAW 320000
#define E_TOT (E_RAW + N_NODES)
#define BN_EPS 1e-5f

// ---------------- scratch (device globals) ----------------
static __device__ __align__(16) __half g_h1h[N_NODES * NHC];  // fp16 projected features
static __device__ float g_skip[N_NODES * NC];
static __device__ float g_es[N_NODES * NH];
static __device__ float g_ed[N_NODES * NH];
static __device__ float g_acc[N_NODES * NC];
static __device__ float g_hmid[N_NODES * NC];
static __device__ float g_sums[NC], g_sumsq[NC], g_scale[NC], g_shift[NC];
static __device__ int   g_cnt[N_NODES];
static __device__ int   g_rowptr[N_NODES + 1];
static __device__ int   g_cursor[N_NODES];
static __device__ int   g_csrc[E_TOT];

__device__ __forceinline__ float gelu_exact(float x) {
    return 0.5f * x * (1.f + erff(x * 0.70710678118654752440f));
}

// ================= CSR construction =================
__global__ void zero_cnt_kernel(int n) {
    int i = blockIdx.x * blockDim.x + threadIdx.x;
    if (i < n) g_cnt[i] = 0;
}

__global__ void hist_kernel(const int* __restrict__ ei, int E, int etot) {
    int e = blockIdx.x * blockDim.x + threadIdx.x;
    if (e >= etot) return;
    int d = (e < E) ? ei[E + e] : (e - E);
    atomicAdd(&g_cnt[d], 1);
}

__global__ void __launch_bounds__(1024) scan_kernel(int n) {
    const int PER = 20;
    int t = threadIdx.x;
    int base = t * PER;
    int v[PER];
    int s = 0;
#pragma unroll
    for (int i = 0; i < PER; i++) {
        v[i] = (base + i < n) ? g_cnt[base + i] : 0;
        s += v[i];
    }
    __shared__ int sh[1024];
    sh[t] = s;
    __syncthreads();
    for (int off = 1; off < 1024; off <<= 1) {
        int x = (t >= off) ? sh[t - off] : 0;
        __syncthreads();
        sh[t] += x;
        __syncthreads();
    }
    int run = sh[t] - s;
#pragma unroll
    for (int i = 0; i < PER; i++) {
        if (base + i < n) {
            g_rowptr[base + i] = run;
            g_cursor[base + i] = run;
        }
        run += v[i];
    }
    if (t == 1023) g_rowptr[n] = sh[1023];
}

__global__ void scatter_kernel(const int* __restrict__ ei, int E, int etot) {
    int e = blockIdx.x * blockDim.x + threadIdx.x;
    if (e >= etot) return;
    int s, d;
    if (e < E) { s = ei[e]; d = ei[E + e]; } else { s = e - E; d = s; }
    int pos = atomicAdd(&g_cursor[d], 1);
    g_csrc[pos] = s;
}

// ================= GEMM: C = A[n,K]@B[K,ncols], tile 128x64xK32 =============
// ATTN variant: writes fp16 C (g_h1h) and emits g_es/g_ed for head blockIdx.y.
template <bool ATTN>
__global__ void __launch_bounds__(256) gemm_kernel(
    const float* __restrict__ A, const float* __restrict__ B,
    float* __restrict__ C, __half* __restrict__ Ch, int n, int K, int ncols,
    const float* __restrict__ asrc, const float* __restrict__ adst)
{
    __shared__ float As[32 * 132];
    __shared__ float Bs[32 * 64];
    const int tid = threadIdx.x;
    const int tx = tid & 15, ty = tid >> 4;
    const int bm = blockIdx.x * 128, bn = blockIdx.y * 64;

    float acc[8][4];
#pragma unroll
    for (int r = 0; r < 8; r++)
#pragma unroll
        for (int j = 0; j < 4; j++) acc[r][j] = 0.f;

    const int lm = tid >> 1;
    const int kh = (tid & 1) * 16;

    for (int k0 = 0; k0 < K; k0 += 32) {
        {
            int row = bm + lm;
            const float* Arow = A + (size_t)row * K + k0 + kh;
#pragma unroll
            for (int u = 0; u < 4; u++) {
                float4 a = (row < n) ? *(const float4*)(Arow + 4 * u)
                                     : make_float4(0.f, 0.f, 0.f, 0.f);
                As[(kh + 4 * u + 0) * 132 + lm] = a.x;
                As[(kh + 4 * u + 1) * 132 + lm] = a.y;
                As[(kh + 4 * u + 2) * 132 + lm] = a.z;
                As[(kh + 4 * u + 3) * 132 + lm] = a.w;
            }
        }
        {
            int kr = tid >> 3, c = (tid & 7) * 8;
            const float* Brow = B + (size_t)(k0 + kr) * ncols + bn + c;
            *(float4*)&Bs[kr * 64 + c]     = *(const float4*)(Brow);
            *(float4*)&Bs[kr * 64 + c + 4] = *(const float4*)(Brow + 4);
        }
        __syncthreads();
#pragma unroll
        for (int k = 0; k < 32; k++) {
            float4 a0 = *(const float4*)&As[k * 132 + ty * 8];
            float4 a1 = *(const float4*)&As[k * 132 + ty * 8 + 4];
            float4 b  = *(const float4*)&Bs[k * 64 + tx * 4];
            acc[0][0] += a0.x * b.x; acc[0][1] += a0.x * b.y; acc[0][2] += a0.x * b.z; acc[0][3] += a0.x * b.w;
            acc[1][0] += a0.y * b.x; acc[1][1] += a0.y * b.y; acc[1][2] += a0.y * b.z; acc[1][3] += a0.y * b.w;
            acc[2][0] += a0.z * b.x; acc[2][1] += a0.z * b.y; acc[2][2] += a0.z * b.z; acc[2][3] += a0.z * b.w;
            acc[3][0] += a0.w * b.x; acc[3][1] += a0.w * b.y; acc[3][2] += a0.w * b.z; acc[3][3] += a0.w * b.w;
            acc[4][0] += a1.x * b.x; acc[4][1] += a1.x * b.y; acc[4][2] += a1.x * b.z; acc[4][3] += a1.x * b.w;
            acc[5][0] += a1.y * b.x; acc[5][1] += a1.y * b.y; acc[5][2] += a1.y * b.z; acc[5][3] += a1.y * b.w;
            acc[6][0] += a1.z * b.x; acc[6][1] += a1.z * b.y; acc[6][2] += a1.z * b.z; acc[6][3] += a1.z * b.w;
            acc[7][0] += a1.w * b.x; acc[7][1] += a1.w * b.y; acc[7][2] += a1.w * b.z; acc[7][3] += a1.w * b.w;
        }
        __syncthreads();
    }

#pragma unroll
    for (int r = 0; r < 8; r++) {
        int row = bm + ty * 8 + r;
        if (row < n) {
            if (ATTN) {
                __half2 p0 = __floats2half2_rn(acc[r][0], acc[r][1]);
                __half2 p1 = __floats2half2_rn(acc[r][2], acc[r][3]);
                uint2 u;
                u.x = *reinterpret_cast<unsigned*>(&p0);
                u.y = *reinterpret_cast<unsigned*>(&p1);
                *(uint2*)&Ch[(size_t)row * ncols + bn + tx * 4] = u;
            } else {
                float4 v = make_float4(acc[r][0], acc[r][1], acc[r][2], acc[r][3]);
                *(float4*)&C[(size_t)row * ncols + bn + tx * 4] = v;
            }
        }
    }
    if (ATTN) {
        float avs[4], avd[4];
#pragma unroll
        for (int j = 0; j < 4; j++) {
            avs[j] = asrc[bn + tx * 4 + j];
            avd[j] = adst[bn + tx * 4 + j];
        }
        float* Ses = As;
        float* Sed = As + 2048;
#pragma unroll
        for (int r = 0; r < 8; r++) {
            float ps = acc[r][0] * avs[0] + acc[r][1] * avs[1] + acc[r][2] * avs[2] + acc[r][3] * avs[3];
            float pd = acc[r][0] * avd[0] + acc[r][1] * avd[1] + acc[r][2] * avd[2] + acc[r][3] * avd[3];
            Ses[(ty * 8 + r) * 16 + tx] = ps;
            Sed[(ty * 8 + r) * 16 + tx] = pd;
        }
        __syncthreads();
        if (tid < 128) {
            int row = bm + tid;
            if (row < n) {
                float s = 0.f, d2 = 0.f;
#pragma unroll
                for (int j = 0; j < 16; j++) {
                    s  += Ses[tid * 16 + j];
                    d2 += Sed[tid * 16 + j];
                }
                g_es[row * 4 + blockIdx.y] = s;
                g_ed[row * 4 + blockIdx.y] = d2;
            }
        }
    }
}

// == fused softmax + gather: warp per dst node; p computed inline; fp16 h ====
// lane = head(2b) x channel-octet(3b): lane reads 8 contiguous halves of one
// head; heads combined by butterfly shuffle at the end; softmax norm + 0.25
// head-mean folded into the final scale.
__global__ void __launch_bounds__(256) aggregate_kernel(int n) {
    int w = (blockIdx.x * blockDim.x + threadIdx.x) >> 5;
    int lane = threadIdx.x & 31;
    if (w >= n) return;
    const int h = lane >> 3;
    const int cb = (lane & 7) * 8;
    int beg = g_rowptr[w], end = g_rowptr[w + 1];
    float edv = g_ed[w * 4 + h];

    float a0 = 0.f, a1 = 0.f, a2 = 0.f, a3 = 0.f;
    float a4 = 0.f, a5 = 0.f, a6 = 0.f, a7 = 0.f;
    float s = 0.f;
    const __half* hb = g_h1h + h * 64 + cb;

#pragma unroll 2
    for (int pos = beg; pos < end; pos++) {
        int src = g_csrc[pos];
        float e = g_es[src * 4 + h] + edv;
        e = e > 0.f ? e : 0.2f * e;
        float p = __expf(e);
        s += p;
        uint4 v = *(const uint4*)(hb + (size_t)src * NHC);
        float2 f0 = __half22float2(*(__half2*)&v.x);
        float2 f1 = __half22float2(*(__half2*)&v.y);
        float2 f2 = __half22float2(*(__half2*)&v.z);
        float2 f3 = __half22float2(*(__half2*)&v.w);
        a0 += p * f0.x; a1 += p * f0.y;
        a2 += p * f1.x; a3 += p * f1.y;
        a4 += p * f2.x; a5 += p * f2.y;
        a6 += p * f3.x; a7 += p * f3.y;
    }
    float inv = 0.25f / (s + 1e-16f);
    float a[8] = {a0 * inv, a1 * inv, a2 * inv, a3 * inv,
                  a4 * inv, a5 * inv, a6 * inv, a7 * inv};
#pragma unroll
    for (int j = 0; j < 8; j++) {
        a[j] += __shfl_xor_sync(0xffffffffu, a[j], 8);
        a[j] += __shfl_xor_sync(0xffffffffu, a[j], 16);
    }
    if (lane < 8) {
        *(float4*)&g_acc[w * NC + lane * 8]     = make_float4(a[0], a[1], a[2], a[3]);
        *(float4*)&g_acc[w * NC + lane * 8 + 4] = make_float4(a[4], a[5], a[6], a[7]);
    }
}

// ================= BatchNorm =================
__global__ void zero_stats_kernel() {
    int c = threadIdx.x;
    if (c < NC) { g_sums[c] = 0.f; g_sumsq[c] = 0.f; }
}

__global__ void bn_stats_kernel(int n) {
    __shared__ float ssum[256], ssq[256];
    int c = threadIdx.x & 63, rq = threadIdx.x >> 6;
    int r0 = blockIdx.x * 128;
    int rend = r0 + 128; if (rend > n) rend = n;
    float s = 0.f, q = 0.f;
    for (int r = r0 + rq; r < rend; r += 4) {
        float v = g_acc[r * NC + c];
        s += v; q += v * v;
    }
    ssum[threadIdx.x] = s; ssq[threadIdx.x] = q;
    __syncthreads();
    if (rq == 0) {
        s = ssum[c] + ssum[c + 64] + ssum[c + 128] + ssum[c + 192];
        q = ssq[c] + ssq[c + 64] + ssq[c + 128] + ssq[c + 192];
        atomicAdd(&g_sums[c], s);
        atomicAdd(&g_sumsq[c], q);
    }
}

// GAT bias b1/b2 cancels inside BatchNorm (additive constant) -> never applied.
__global__ void bn_finalize_kernel(const float* __restrict__ gamma,
                                   const float* __restrict__ beta, int n) {
    int c = threadIdx.x;
    if (c >= NC) return;
    float inv = 1.f / (float)n;
    float mu = g_sums[c] * inv;
    float var = g_sumsq[c] * inv - mu * mu;
    float sc = gamma[c] * rsqrtf(var + BN_EPS);
    g_scale[c] = sc;
    g_shift[c] = beta[c] - mu * sc;
}

// ======= fused epilogue 1: h = gelu(BN(gat1) + skip + bskip) =======
__global__ void fuse1_kernel(const float* __restrict__ bskip, int total) {
    int i = blockIdx.x * blockDim.x + threadIdx.x;
    if (i >= total) return;
    int c = i & 63;
    float x = g_acc[i] * g_scale[c] + g_shift[c] + g_skip[i] + bskip[c];
    g_hmid[i] = gelu_exact(x);
}

// ======= fused epilogue 2 + pool: block per graph =======
__device__ __forceinline__ int lower_bound_dev(const int* arr, int n, int target) {
    int lo = 0, hi = n;
    while (lo < hi) {
        int mid = (lo + hi) >> 1;
        if (arr[mid] < target) lo = mid + 1; else hi = mid;
    }
    return lo;
}

__global__ void fuse2_pool_kernel(const int* __restrict__ batch,
                                  float* __restrict__ out, int n) {
    int g = blockIdx.x;
    __shared__ int bounds[2];
    if (threadIdx.x < 2)
        bounds[threadIdx.x] = lower_bound_dev(batch, n, g + threadIdx.x);
    __syncthreads();
    int lo = bounds[0], hi = bounds[1];
    int c = threadIdx.x & 63, rq = threadIdx.x >> 6;
    float s = 0.f;
    for (int node = lo + rq; node < hi; node += 4) {
        float x = g_acc[node * NC + c] * g_scale[c] + g_shift[c] + g_hmid[node * NC + c];
        s += gelu_exact(x);
    }
    __shared__ float red[256];
    red[threadIdx.x] = s;
    __syncthreads();
    if (threadIdx.x < 64) {
        float tot = red[c] + red[c + 64] + red[c + 128] + red[c + 192];
        out[g * NC + c] = tot / fmaxf((float)(hi - lo), 1.f);
    }
}

// ================= launch =================
extern "C" void kernel_launch(void* const* d_in, const int* in_sizes, int n_in,
                              void* d_out, int out_size) {
    const float* x      = (const float*)d_in[0];
    const float* W1     = (const float*)d_in[1];
    const float* a_src1 = (const float*)d_in[2];
    const float* a_dst1 = (const float*)d_in[3];
    const float* Wskip  = (const float*)d_in[5];
    const float* bskip  = (const float*)d_in[6];
    const float* g1     = (const float*)d_in[7];
    const float* be1    = (const float*)d_in[8];
    const float* W2     = (const float*)d_in[9];
    const float* a_src2 = (const float*)d_in[10];
    const float* a_dst2 = (const float*)d_in[11];
    const float* g2     = (const float*)d_in[13];
    const float* be2    = (const float*)d_in[14];
    const int*   ei     = (const int*)d_in[15];
    const int*   batch  = (const int*)d_in[16];
    float* out = (float*)d_out;

    int n = in_sizes[0] / NFIN;
    int E = in_sizes[15] / 2;
    int etot = E + n;

    __half* p_h1h;
    float *p_skip, *p_hmid;
    cudaGetSymbolAddress((void**)&p_h1h, g_h1h);
    cudaGetSymbolAddress((void**)&p_skip, g_skip);
    cudaGetSymbolAddress((void**)&p_hmid, g_hmid);

    int eb = (etot + 255) / 256;
    int gx = (n + 127) / 128;
    int fb = (n * NC + 255) / 256;
    int ab = (n * 32 + 255) / 256;

    // CSR (shared by both layers)
    zero_cnt_kernel<<<(n + 255) / 256, 256>>>(n);
    hist_kernel<<<eb, 256>>>(ei, E, etot);
    scan_kernel<<<1, 1024>>>(n);
    scatter_kernel<<<eb, 256>>>(ei, E, etot);

    // ---- layer 1
    gemm_kernel<true><<<dim3(gx, 4), 256>>>(x, W1, nullptr, p_h1h, n, NFIN, NHC, a_src1, a_dst1);
    gemm_kernel<false><<<dim3(gx, 1), 256>>>(x, Wskip, p_skip, nullptr, n, NFIN, NC, nullptr, nullptr);
    aggregate_kernel<<<ab, 256>>>(n);
    zero_stats_kernel<<<1, 64>>>();
    bn_stats_kernel<<<(n + 127) / 128, 256>>>(n);
    bn_finalize_kernel<<<1, 64>>>(g1, be1, n);
    fuse1_kernel<<<fb, 256>>>(bskip, n * NC);

    // ---- layer 2
    gemm_kernel<true><<<dim3(gx, 4), 256>>>(p_hmid, W2, nullptr, p_h1h, n, NC, NHC, a_src2, a_dst2);
    aggregate_kernel<<<ab, 256>>>(n);
    zero_stats_kernel<<<1, 64>>>();
    bn_stats_kernel<<<(n + 127) / 128, 256>>>(n);
    bn_finalize_kernel<<<1, 64>>>(g2, be2, n);

    // ---- fused epilogue 2 + mean pool
    fuse2_pool_kernel<<<N_GRAPH, 256>>>(batch, out, n);
}

// round 4
// speedup vs baseline: 1.8121x; 1.2926x over previous
#include <cuda_runtime.h>
#include <cuda_fp16.h>
#include <math.h>

#define N_NODES 20000
#define N_GRAPH 64
#define NH 4
#define NC 64
#define NFIN 128
#define NHC 256
#define E_RAW 320000
#define E_TOT (E_RAW + N_NODES)
#define BN_EPS 1e-5f

// ---------------- scratch (device globals) ----------------
static __device__ __align__(16) __half g_h1h[N_NODES * NHC];
static __device__ __align__(16) __half g_xh[N_NODES * NFIN];
static __device__ __align__(16) __half g_hmidh[N_NODES * NC];
static __device__ float g_skip[N_NODES * NC];
static __device__ float g_es[N_NODES * NH];
static __device__ float g_ed[N_NODES * NH];
static __device__ float g_acc[N_NODES * NC];
static __device__ float g_hmid[N_NODES * NC];
static __device__ float g_sums[NC], g_sumsq[NC], g_scale[NC], g_shift[NC];
static __device__ int   g_cnt[N_NODES];
static __device__ int   g_rowptr[N_NODES + 1];
static __device__ int   g_cursor[N_NODES];
static __device__ int   g_csrc[E_TOT];

__device__ __forceinline__ float gelu_exact(float x) {
    return 0.5f * x * (1.f + erff(x * 0.70710678118654752440f));
}

__device__ __forceinline__ unsigned smem_u32(const void* p) {
    return (unsigned)__cvta_generic_to_shared(p);
}

__device__ __forceinline__ void ldm_x4(unsigned r[4], unsigned addr) {
    asm volatile("ldmatrix.sync.aligned.m8n8.x4.shared.b16 {%0,%1,%2,%3}, [%4];"
        : "=r"(r[0]), "=r"(r[1]), "=r"(r[2]), "=r"(r[3]) : "r"(addr));
}
__device__ __forceinline__ void ldm_x2t(unsigned r[2], unsigned addr) {
    asm volatile("ldmatrix.sync.aligned.m8n8.x2.trans.shared.b16 {%0,%1}, [%2];"
        : "=r"(r[0]), "=r"(r[1]) : "r"(addr));
}
__device__ __forceinline__ void mma16816(float c[4], const unsigned a[4], const unsigned b[2]) {
    asm volatile("mma.sync.aligned.m16n8k16.row.col.f32.f16.f16.f32 "
        "{%0,%1,%2,%3}, {%4,%5,%6,%7}, {%8,%9}, {%0,%1,%2,%3};"
        : "+f"(c[0]), "+f"(c[1]), "+f"(c[2]), "+f"(c[3])
        : "r"(a[0]), "r"(a[1]), "r"(a[2]), "r"(a[3]), "r"(b[0]), "r"(b[1]));
}

// ================= fp32 -> fp16 conversion (vectorized by 4) ================
__global__ void conv_f2h_kernel(const float* __restrict__ src, __half* __restrict__ dst, int total4) {
    int i = blockIdx.x * blockDim.x + threadIdx.x;
    if (i >= total4) return;
    float4 v = ((const float4*)src)[i];
    __half2 h0 = __floats2half2_rn(v.x, v.y);
    __half2 h1 = __floats2half2_rn(v.z, v.w);
    ((uint2*)dst)[i] = make_uint2(*(unsigned*)&h0, *(unsigned*)&h1);
}

// ================= CSR construction =================
__global__ void zero_cnt_kernel(int n) {
    int i = blockIdx.x * blockDim.x + threadIdx.x;
    if (i < n) g_cnt[i] = 0;
}

__global__ void hist_kernel(const int* __restrict__ ei, int E, int etot) {
    int e = blockIdx.x * blockDim.x + threadIdx.x;
    if (e >= etot) return;
    int d = (e < E) ? ei[E + e] : (e - E);
    atomicAdd(&g_cnt[d], 1);
}

__global__ void __launch_bounds__(1024) scan_kernel(int n) {
    const int PER = 20;
    int t = threadIdx.x;
    int base = t * PER;
    int v[PER];
    int s = 0;
#pragma unroll
    for (int i = 0; i < PER; i++) {
        v[i] = (base + i < n) ? g_cnt[base + i] : 0;
        s += v[i];
    }
    __shared__ int sh[1024];
    sh[t] = s;
    __syncthreads();
    for (int off = 1; off < 1024; off <<= 1) {
        int x = (t >= off) ? sh[t - off] : 0;
        __syncthreads();
        sh[t] += x;
        __syncthreads();
    }
    int run = sh[t] - s;
#pragma unroll
    for (int i = 0; i < PER; i++) {
        if (base + i < n) {
            g_rowptr[base + i] = run;
            g_cursor[base + i] = run;
        }
        run += v[i];
    }
    if (t == 1023) g_rowptr[n] = sh[1023];
}

__global__ void scatter_kernel(const int* __restrict__ ei, int E, int etot) {
    int e = blockIdx.x * blockDim.x + threadIdx.x;
    if (e >= etot) return;
    int s, d;
    if (e < E) { s = ei[e]; d = ei[E + e]; } else { s = e - E; d = s; }
    int pos = atomicAdd(&g_cursor[d], 1);
    g_csrc[pos] = s;
}

// ========== HMMA GEMM: C[n,ncols] = A[n,K](fp16) @ B[K,ncols](fp32->fp16) ==
// Block tile 128x64, K staged 64 at a time. 8 warps: 4 (M) x 2 (N), each warp
// 32x32 via 2x4 m16n8k16 mma. ATTN: writes fp16 C (g_h1h) + per-head es/ed
// (head = blockIdx.y); else writes fp32 C.
template <bool ATTN>
__global__ void __launch_bounds__(256) hgemm_kernel(
    const __half* __restrict__ Ah, const float* __restrict__ Bf,
    float* __restrict__ Cf, __half* __restrict__ Ch,
    int n, int K, int ncols,
    const float* __restrict__ asrc, const float* __restrict__ adst)
{
    __shared__ __half As[128 * 72];
    __shared__ __half Bs[64 * 72];
    const int tid = threadIdx.x;
    const int l = tid & 31, w = tid >> 5;
    const int wr = w >> 1, wc = w & 1;
    const int bm = blockIdx.x * 128, bn = blockIdx.y * 64;

    float c[2][4][4];
#pragma unroll
    for (int mt = 0; mt < 2; mt++)
#pragma unroll
        for (int nt = 0; nt < 4; nt++)
#pragma unroll
            for (int j = 0; j < 4; j++) c[mt][nt][j] = 0.f;

    for (int k0 = 0; k0 < K; k0 += 64) {
        // load A tile: thread t -> row t>>1, 32 halves at (t&1)*32
        {
            int rlocal = tid >> 1;
            int row = bm + rlocal;
            int colh = (tid & 1) * 32;
            uint4 z = make_uint4(0, 0, 0, 0);
            const uint4* src = (const uint4*)(Ah + (size_t)row * K + k0 + colh);
            uint4 v0 = (row < n) ? src[0] : z;
            uint4 v1 = (row < n) ? src[1] : z;
            uint4 v2 = (row < n) ? src[2] : z;
            uint4 v3 = (row < n) ? src[3] : z;
            uint4* dstp = (uint4*)(As + rlocal * 72 + colh);
            dstp[0] = v0; dstp[1] = v1; dstp[2] = v2; dstp[3] = v3;
        }
        // load B tile (fp32 -> fp16): thread t -> row t>>2, 16 floats at (t&3)*16
        {
            int row = tid >> 2, colh = (tid & 3) * 16;
            const float4* src = (const float4*)(Bf + (size_t)(k0 + row) * ncols + bn + colh);
            float4 f0 = src[0], f1 = src[1], f2 = src[2], f3 = src[3];
            __half2* dstp = (__half2*)(Bs + row * 72 + colh);
            dstp[0] = __floats2half2_rn(f0.x, f0.y);
            dstp[1] = __floats2half2_rn(f0.z, f0.w);
            dstp[2] = __floats2half2_rn(f1.x, f1.y);
            dstp[3] = __floats2half2_rn(f1.z, f1.w);
            dstp[4] = __floats2half2_rn(f2.x, f2.y);
            dstp[5] = __floats2half2_rn(f2.z, f2.w);
            dstp[6] = __floats2half2_rn(f3.x, f3.y);
            dstp[7] = __floats2half2_rn(f3.z, f3.w);
        }
        __syncthreads();
#pragma unroll
        for (int kk = 0; kk < 4; kk++) {
            unsigned af[2][4];
#pragma unroll
            for (int mt = 0; mt < 2; mt++) {
                int rowA = wr * 32 + mt * 16 + (l & 15);
                int colA = kk * 16 + ((l >> 4) << 3);
                ldm_x4(af[mt], smem_u32(As + rowA * 72 + colA));
            }
            unsigned bf[4][2];
#pragma unroll
            for (int nt = 0; nt < 4; nt++) {
                int rowB = kk * 16 + (l & 15);
                int colB = wc * 32 + nt * 8;
                ldm_x2t(bf[nt], smem_u32(Bs + rowB * 72 + colB));
            }
#pragma unroll
            for (int mt = 0; mt < 2; mt++)
#pragma unroll
                for (int nt = 0; nt < 4; nt++)
                    mma16816(c[mt][nt], af[mt], bf[nt]);
        }
        __syncthreads();
    }

    if (ATTN) {
        float as8[8], ad8[8];
        int cb = wc * 32 + 2 * (l & 3);
#pragma unroll
        for (int nt = 0; nt < 4; nt++) {
            as8[2 * nt]     = asrc[bn + cb + nt * 8];
            as8[2 * nt + 1] = asrc[bn + cb + nt * 8 + 1];
            ad8[2 * nt]     = adst[bn + cb + nt * 8];
            ad8[2 * nt + 1] = adst[bn + cb + nt * 8 + 1];
        }
        float* Ses = (float*)As;        // [128][2]
        float* Sed = Ses + 256;
#pragma unroll
        for (int mt = 0; mt < 2; mt++) {
            int r0 = bm + wr * 32 + mt * 16 + (l >> 2);
            int r1 = r0 + 8;
            float plo = 0.f, phi = 0.f, qlo = 0.f, qhi = 0.f;
#pragma unroll
            for (int nt = 0; nt < 4; nt++) {
                float c0 = c[mt][nt][0], c1 = c[mt][nt][1];
                float c2 = c[mt][nt][2], c3 = c[mt][nt][3];
                int col = bn + wc * 32 + nt * 8 + 2 * (l & 3);
                if (r0 < n) *(__half2*)&Ch[(size_t)r0 * ncols + col] = __floats2half2_rn(c0, c1);
                if (r1 < n) *(__half2*)&Ch[(size_t)r1 * ncols + col] = __floats2half2_rn(c2, c3);
                plo += c0 * as8[2 * nt] + c1 * as8[2 * nt + 1];
                phi += c2 * as8[2 * nt] + c3 * as8[2 * nt + 1];
                qlo += c0 * ad8[2 * nt] + c1 * ad8[2 * nt + 1];
                qhi += c2 * ad8[2 * nt] + c3 * ad8[2 * nt + 1];
            }
#pragma unroll
            for (int off = 1; off <= 2; off <<= 1) {
                plo += __shfl_xor_sync(0xffffffffu, plo, off);
                phi += __shfl_xor_sync(0xffffffffu, phi, off);
                qlo += __shfl_xor_sync(0xffffffffu, qlo, off);
                qhi += __shfl_xor_sync(0xffffffffu, qhi, off);
            }
            if ((l & 3) == 0) {
                int rr = wr * 32 + mt * 16 + (l >> 2);
                Ses[rr * 2 + wc] = plo;
                Ses[(rr + 8) * 2 + wc] = phi;
                Sed[rr * 2 + wc] = qlo;
                Sed[(rr + 8) * 2 + wc] = qhi;
            }
        }
        __syncthreads();
        if (tid < 128) {
            int row = bm + tid;
            if (row < n) {
                g_es[row * 4 + blockIdx.y] = Ses[tid * 2] + Ses[tid * 2 + 1];
                g_ed[row * 4 + blockIdx.y] = Sed[tid * 2] + Sed[tid * 2 + 1];
            }
        }
    } else {
#pragma unroll
        for (int mt = 0; mt < 2; mt++) {
            int r0 = bm + wr * 32 + mt * 16 + (l >> 2);
            int r1 = r0 + 8;
#pragma unroll
            for (int nt = 0; nt < 4; nt++) {
                int col = bn + wc * 32 + nt * 8 + 2 * (l & 3);
                if (r0 < n) *(float2*)&Cf[(size_t)r0 * ncols + col] =
                    make_float2(c[mt][nt][0], c[mt][nt][1]);
                if (r1 < n) *(float2*)&Cf[(size_t)r1 * ncols + col] =
                    make_float2(c[mt][nt][2], c[mt][nt][3]);
            }
        }
    }
}

// == fused softmax + gather: warp per dst node ====
__global__ void __launch_bounds__(256) aggregate_kernel(int n) {
    int w = (blockIdx.x * blockDim.x + threadIdx.x) >> 5;
    int lane = threadIdx.x & 31;
    if (w >= n) return;
    const int h = lane >> 3;
    const int cb = (lane & 7) * 8;
    int beg = g_rowptr[w], end = g_rowptr[w + 1];
    float edv = g_ed[w * 4 + h];

    float a0 = 0.f, a1 = 0.f, a2 = 0.f, a3 = 0.f;
    float a4 = 0.f, a5 = 0.f, a6 = 0.f, a7 = 0.f;
    float s = 0.f;
    const __half* hb = g_h1h + h * 64 + cb;

#pragma unroll 2
    for (int pos = beg; pos < end; pos++) {
        int src = g_csrc[pos];
        float e = g_es[src * 4 + h] + edv;
        e = e > 0.f ? e : 0.2f * e;
        float p = __expf(e);
        s += p;
        uint4 v = *(const uint4*)(hb + (size_t)src * NHC);
        float2 f0 = __half22float2(*(__half2*)&v.x);
        float2 f1 = __half22float2(*(__half2*)&v.y);
        float2 f2 = __half22float2(*(__half2*)&v.z);
        float2 f3 = __half22float2(*(__half2*)&v.w);
        a0 += p * f0.x; a1 += p * f0.y;
        a2 += p * f1.x; a3 += p * f1.y;
        a4 += p * f2.x; a5 += p * f2.y;
        a6 += p * f3.x; a7 += p * f3.y;
    }
    float inv = 0.25f / (s + 1e-16f);
    float a[8] = {a0 * inv, a1 * inv, a2 * inv, a3 * inv,
                  a4 * inv, a5 * inv, a6 * inv, a7 * inv};
#pragma unroll
    for (int j = 0; j < 8; j++) {
        a[j] += __shfl_xor_sync(0xffffffffu, a[j], 8);
        a[j] += __shfl_xor_sync(0xffffffffu, a[j], 16);
    }
    if (lane < 8) {
        *(float4*)&g_acc[w * NC + lane * 8]     = make_float4(a[0], a[1], a[2], a[3]);
        *(float4*)&g_acc[w * NC + lane * 8 + 4] = make_float4(a[4], a[5], a[6], a[7]);
    }
}

// ================= BatchNorm =================
__global__ void zero_stats_kernel() {
    int c = threadIdx.x;
    if (c < NC) { g_sums[c] = 0.f; g_sumsq[c] = 0.f; }
}

__global__ void bn_stats_kernel(int n) {
    __shared__ float ssum[256], ssq[256];
    int c = threadIdx.x & 63, rq = threadIdx.x >> 6;
    int r0 = blockIdx.x * 128;
    int rend = r0 + 128; if (rend > n) rend = n;
    float s = 0.f, q = 0.f;
    for (int r = r0 + rq; r < rend; r += 4) {
        float v = g_acc[r * NC + c];
        s += v; q += v * v;
    }
    ssum[threadIdx.x] = s; ssq[threadIdx.x] = q;
    __syncthreads();
    if (rq == 0) {
        s = ssum[c] + ssum[c + 64] + ssum[c + 128] + ssum[c + 192];
        q = ssq[c] + ssq[c + 64] + ssq[c + 128] + ssq[c + 192];
        atomicAdd(&g_sums[c], s);
        atomicAdd(&g_sumsq[c], q);
    }
}

// GAT bias b1/b2 cancels inside BatchNorm (additive constant) -> never applied.
__global__ void bn_finalize_kernel(const float* __restrict__ gamma,
                                   const float* __restrict__ beta, int n) {
    int c = threadIdx.x;
    if (c >= NC) return;
    float inv = 1.f / (float)n;
    float mu = g_sums[c] * inv;
    float var = g_sumsq[c] * inv - mu * mu;
    float sc = gamma[c] * rsqrtf(var + BN_EPS);
    g_scale[c] = sc;
    g_shift[c] = beta[c] - mu * sc;
}

// ======= fused epilogue 1: h = gelu(BN(gat1) + skip + bskip); fp32+fp16 =====
__global__ void fuse1_kernel(const float* __restrict__ bskip, int total) {
    int i = blockIdx.x * blockDim.x + threadIdx.x;
    if (i >= total) return;
    int c = i & 63;
    float x = g_acc[i] * g_scale[c] + g_shift[c] + g_skip[i] + bskip[c];
    float y = gelu_exact(x);
    g_hmid[i] = y;
    g_hmidh[i] = __float2half_rn(y);
}

// ======= fused epilogue 2 + pool: block per graph =======
__device__ __forceinline__ int lower_bound_dev(const int* arr, int n, int target) {
    int lo = 0, hi = n;
    while (lo < hi) {
        int mid = (lo + hi) >> 1;
        if (arr[mid] < target) lo = mid + 1; else hi = mid;
    }
    return lo;
}

__global__ void fuse2_pool_kernel(const int* __restrict__ batch,
                                  float* __restrict__ out, int n) {
    int g = blockIdx.x;
    __shared__ int bounds[2];
    if (threadIdx.x < 2)
        bounds[threadIdx.x] = lower_bound_dev(batch, n, g + threadIdx.x);
    __syncthreads();
    int lo = bounds[0], hi = bounds[1];
    int c = threadIdx.x & 63, rq = threadIdx.x >> 6;
    float s = 0.f;
    for (int node = lo + rq; node < hi; node += 4) {
        float x = g_acc[node * NC + c] * g_scale[c] + g_shift[c] + g_hmid[node * NC + c];
        s += gelu_exact(x);
    }
    __shared__ float red[256];
    red[threadIdx.x] = s;
    __syncthreads();
    if (threadIdx.x < 64) {
        float tot = red[c] + red[c + 64] + red[c + 128] + red[c + 192];
        out[g * NC + c] = tot / fmaxf((float)(hi - lo), 1.f);
    }
}

// ================= launch =================
extern "C" void kernel_launch(void* const* d_in, const int* in_sizes, int n_in,
                              void* d_out, int out_size) {
    const float* x      = (const float*)d_in[0];
    const float* W1     = (const float*)d_in[1];
    const float* a_src1 = (const float*)d_in[2];
    const float* a_dst1 = (const float*)d_in[3];
    const float* Wskip  = (const float*)d_in[5];
    const float* bskip  = (const float*)d_in[6];
    const float* g1     = (const float*)d_in[7];
    const float* be1    = (const float*)d_in[8];
    const float* W2     = (const float*)d_in[9];
    const float* a_src2 = (const float*)d_in[10];
    const float* a_dst2 = (const float*)d_in[11];
    const float* g2     = (const float*)d_in[13];
    const float* be2    = (const float*)d_in[14];
    const int*   ei     = (const int*)d_in[15];
    const int*   batch  = (const int*)d_in[16];
    float* out = (float*)d_out;

    int n = in_sizes[0] / NFIN;
    int E = in_sizes[15] / 2;
    int etot = E + n;

    __half *p_h1h, *p_xh, *p_hmidh;
    float *p_skip;
    cudaGetSymbolAddress((void**)&p_h1h, g_h1h);
    cudaGetSymbolAddress((void**)&p_xh, g_xh);
    cudaGetSymbolAddress((void**)&p_hmidh, g_hmidh);
    cudaGetSymbolAddress((void**)&p_skip, g_skip);

    int eb = (etot + 255) / 256;
    int gx = (n + 127) / 128;
    int fb = (n * NC + 255) / 256;
    int ab = (n * 32 + 255) / 256;

    // CSR (shared by both layers)
    zero_cnt_kernel<<<(n + 255) / 256, 256>>>(n);
    hist_kernel<<<eb, 256>>>(ei, E, etot);
    scan_kernel<<<1, 1024>>>(n);
    scatter_kernel<<<eb, 256>>>(ei, E, etot);

    // x -> fp16
    int x4 = n * NFIN / 4;
    conv_f2h_kernel<<<(x4 + 255) / 256, 256>>>(x, p_xh, x4);

    // ---- layer 1
    hgemm_kernel<true><<<dim3(gx, 4), 256>>>(p_xh, W1, nullptr, p_h1h, n, NFIN, NHC, a_src1, a_dst1);
    hgemm_kernel<false><<<dim3(gx, 1), 256>>>(p_xh, Wskip, p_skip, nullptr, n, NFIN, NC, nullptr, nullptr);
    aggregate_kernel<<<ab, 256>>>(n);
    zero_stats_kernel<<<1, 64>>>();
    bn_stats_kernel<<<(n + 127) / 128, 256>>>(n);
    bn_finalize_kernel<<<1, 64>>>(g1, be1, n);
    fuse1_kernel<<<fb, 256>>>(bskip, n * NC);

    // ---- layer 2
    hgemm_kernel<true><<<dim3(gx, 4), 256>>>(p_hmidh, W2, nullptr, p_h1h, n, NC, NHC, a_src2, a_dst2);
    aggregate_kernel<<<ab, 256>>>(n);
    zero_stats_kernel<<<1, 64>>>();
    bn_stats_kernel<<<(n + 127) / 128, 256>>>(n);
    bn_finalize_kernel<<<1, 64>>>(g2, be2, n);

    // ---- fused epilogue 2 + mean pool
    fuse2_pool_kernel<<<N_GRAPH, 256>>>(batch, out, n);
}

// round 6
// speedup vs baseline: 1.8625x; 1.0278x over previous
#include <cuda_runtime.h>
#include <cuda_fp16.h>
#include <math.h>

#define N_NODES 20000
#define N_GRAPH 64
#define NH 4
#define NC 64
#define NFIN 128
#define NHC 256
#define E_RAW 320000
#define E_TOT (E_RAW + N_NODES)
#define BN_EPS 1e-5f

// ---------------- scratch (device globals) ----------------
static __device__ __align__(16) __half g_h1h[N_NODES * NHC];
static __device__ __align__(16) __half g_hmidh[N_NODES * NC];
static __device__ float g_skip[N_NODES * NC];
static __device__ float g_es[N_NODES * NH];
static __device__ float g_ed[N_NODES * NH];
static __device__ float g_acc[N_NODES * NC];
static __device__ float g_hmid[N_NODES * NC];
static __device__ float g_bnstats[4 * NC];   // sums0, sumsq0, sums1, sumsq1
static __device__ int   g_cnt[N_NODES];
static __device__ int   g_rowptr[N_NODES + 1];
static __device__ int   g_cursor[N_NODES];
static __device__ int   g_csrc[E_TOT];

__device__ __forceinline__ float gelu_exact(float x) {
    return 0.5f * x * (1.f + erff(x * 0.70710678118654752440f));
}

__device__ __forceinline__ unsigned smem_u32(const void* p) {
    return (unsigned)__cvta_generic_to_shared(p);
}

__device__ __forceinline__ void ldm_x4(unsigned r[4], unsigned addr) {
    asm volatile("ldmatrix.sync.aligned.m8n8.x4.shared.b16 {%0,%1,%2,%3}, [%4];"
        : "=r"(r[0]), "=r"(r[1]), "=r"(r[2]), "=r"(r[3]) : "r"(addr));
}
__device__ __forceinline__ void ldm_x2t(unsigned r[2], unsigned addr) {
    asm volatile("ldmatrix.sync.aligned.m8n8.x2.trans.shared.b16 {%0,%1}, [%2];"
        : "=r"(r[0]), "=r"(r[1]) : "r"(addr));
}
__device__ __forceinline__ void mma16816(float c[4], const unsigned a[4], const unsigned b[2]) {
    asm volatile("mma.sync.aligned.m16n8k16.row.col.f32.f16.f16.f32 "
        "{%0,%1,%2,%3}, {%4,%5,%6,%7}, {%8,%9}, {%0,%1,%2,%3};"
        : "+f"(c[0]), "+f"(c[1]), "+f"(c[2]), "+f"(c[3])
        : "r"(a[0]), "r"(a[1]), "r"(a[2]), "r"(a[3]), "r"(b[0]), "r"(b[1]));
}

// ================= CSR construction + stat zeroing =================
__global__ void zero_cnt_kernel(int n) {
    int i = blockIdx.x * blockDim.x + threadIdx.x;
    if (i < n) g_cnt[i] = 0;
    if (i < 4 * NC) g_bnstats[i] = 0.f;
}

__global__ void __launch_bounds__(1024) scan_kernel(int n) {
    const int PER = 20;
    int t = threadIdx.x;
    int base = t * PER;
    int v[PER];
    int s = 0;
#pragma unroll
    for (int i = 0; i < PER; i++) {
        v[i] = (base + i < n) ? g_cnt[base + i] : 0;
        s += v[i];
    }
    __shared__ int sh[1024];
    sh[t] = s;
    __syncthreads();
    for (int off = 1; off < 1024; off <<= 1) {
        int x = (t >= off) ? sh[t - off] : 0;
        __syncthreads();
        sh[t] += x;
        __syncthreads();
    }
    int run = sh[t] - s;
#pragma unroll
    for (int i = 0; i < PER; i++) {
        if (base + i < n) {
            g_rowptr[base + i] = run;
            g_cursor[base + i] = run;
        }
        run += v[i];
    }
    if (t == 1023) g_rowptr[n] = sh[1023];
}

__global__ void scatter_kernel(const int* __restrict__ ei, int E, int etot) {
    int e = blockIdx.x * blockDim.x + threadIdx.x;
    if (e >= etot) return;
    int s, d;
    if (e < E) { s = ei[e]; d = ei[E + e]; } else { s = e - E; d = s; }
    int pos = atomicAdd(&g_cursor[d], 1);
    g_csrc[pos] = s;
}

// ========== HMMA GEMM body: C[n,ncols] = A[n,K] @ B[K,ncols](fp32->fp16) ===
// AF32: A fp32, converted in the smem loader. ATTN: fp16 C + es/ed for `head`.
template <bool ATTN, bool AF32>
__device__ __forceinline__ void gemm_body(
    __half* As, __half* Bs,
    const __half* __restrict__ Ah, const float* __restrict__ Af,
    const float* __restrict__ Bf,
    float* __restrict__ Cf, __half* __restrict__ Ch,
    int n, int K, int ncols, int head, int bx,
    const float* __restrict__ asrc, const float* __restrict__ adst)
{
    const int tid = threadIdx.x;
    const int l = tid & 31, w = tid >> 5;
    const int wr = w >> 1, wc = w & 1;
    const int bm = bx * 128, bn = head * 64;

    float c[2][4][4];
#pragma unroll
    for (int mt = 0; mt < 2; mt++)
#pragma unroll
        for (int nt = 0; nt < 4; nt++)
#pragma unroll
            for (int j = 0; j < 4; j++) c[mt][nt][j] = 0.f;

    for (int k0 = 0; k0 < K; k0 += 64) {
        {
            int rlocal = tid >> 1;
            int row = bm + rlocal;
            int colh = (tid & 1) * 32;
            bool ok = row < n;
            if (AF32) {
                const float4* src = (const float4*)(Af + (size_t)row * K + k0 + colh);
                __half2* dstp = (__half2*)(As + rlocal * 72 + colh);
#pragma unroll
                for (int u = 0; u < 8; u++) {
                    float4 f = ok ? src[u] : make_float4(0.f, 0.f, 0.f, 0.f);
                    dstp[2 * u]     = __floats2half2_rn(f.x, f.y);
                    dstp[2 * u + 1] = __floats2half2_rn(f.z, f.w);
                }
            } else {
                uint4 z = make_uint4(0, 0, 0, 0);
                const uint4* src = (const uint4*)(Ah + (size_t)row * K + k0 + colh);
                uint4 v0 = ok ? src[0] : z;
                uint4 v1 = ok ? src[1] : z;
                uint4 v2 = ok ? src[2] : z;
                uint4 v3 = ok ? src[3] : z;
                uint4* dstp = (uint4*)(As + rlocal * 72 + colh);
                dstp[0] = v0; dstp[1] = v1; dstp[2] = v2; dstp[3] = v3;
            }
        }
        {
            int row = tid >> 2, colh = (tid & 3) * 16;
            const float4* src = (const float4*)(Bf + (size_t)(k0 + row) * ncols + bn + colh);
            float4 f0 = src[0], f1 = src[1], f2 = src[2], f3 = src[3];
            __half2* dstp = (__half2*)(Bs + row * 72 + colh);
            dstp[0] = __floats2half2_rn(f0.x, f0.y);
            dstp[1] = __floats2half2_rn(f0.z, f0.w);
            dstp[2] = __floats2half2_rn(f1.x, f1.y);
            dstp[3] = __floats2half2_rn(f1.z, f1.w);
            dstp[4] = __floats2half2_rn(f2.x, f2.y);
            dstp[5] = __floats2half2_rn(f2.z, f2.w);
            dstp[6] = __floats2half2_rn(f3.x, f3.y);
            dstp[7] = __floats2half2_rn(f3.z, f3.w);
        }
        __syncthreads();
#pragma unroll
        for (int kk = 0; kk < 4; kk++) {
            unsigned af[2][4];
#pragma unroll
            for (int mt = 0; mt < 2; mt++) {
                int rowA = wr * 32 + mt * 16 + (l & 15);
                int colA = kk * 16 + ((l >> 4) << 3);
                ldm_x4(af[mt], smem_u32(As + rowA * 72 + colA));
            }
            unsigned bf[4][2];
#pragma unroll
            for (int nt = 0; nt < 4; nt++) {
                int rowB = kk * 16 + (l & 15);
                int colB = wc * 32 + nt * 8;
                ldm_x2t(bf[nt], smem_u32(Bs + rowB * 72 + colB));
            }
#pragma unroll
            for (int mt = 0; mt < 2; mt++)
#pragma unroll
                for (int nt = 0; nt < 4; nt++)
                    mma16816(c[mt][nt], af[mt], bf[nt]);
        }
        __syncthreads();
    }

    if (ATTN) {
        float as8[8], ad8[8];
        int cb = wc * 32 + 2 * (l & 3);
#pragma unroll
        for (int nt = 0; nt < 4; nt++) {
            as8[2 * nt]     = asrc[bn + cb + nt * 8];
            as8[2 * nt + 1] = asrc[bn + cb + nt * 8 + 1];
            ad8[2 * nt]     = adst[bn + cb + nt * 8];
            ad8[2 * nt + 1] = adst[bn + cb + nt * 8 + 1];
        }
        float* Ses = (float*)As;        // [128][2]
        float* Sed = Ses + 256;
#pragma unroll
        for (int mt = 0; mt < 2; mt++) {
            int r0 = bm + wr * 32 + mt * 16 + (l >> 2);
            int r1 = r0 + 8;
            float plo = 0.f, phi = 0.f, qlo = 0.f, qhi = 0.f;
#pragma unroll
            for (int nt = 0; nt < 4; nt++) {
                float c0 = c[mt][nt][0], c1 = c[mt][nt][1];
                float c2 = c[mt][nt][2], c3 = c[mt][nt][3];
                int col = bn + wc * 32 + nt * 8 + 2 * (l & 3);
                if (r0 < n) *(__half2*)&Ch[(size_t)r0 * ncols + col] = __floats2half2_rn(c0, c1);
                if (r1 < n) *(__half2*)&Ch[(size_t)r1 * ncols + col] = __floats2half2_rn(c2, c3);
                plo += c0 * as8[2 * nt] + c1 * as8[2 * nt + 1];
                phi += c2 * as8[2 * nt] + c3 * as8[2 * nt + 1];
                qlo += c0 * ad8[2 * nt] + c1 * ad8[2 * nt + 1];
                qhi += c2 * ad8[2 * nt] + c3 * ad8[2 * nt + 1];
            }
#pragma unroll
            for (int off = 1; off <= 2; off <<= 1) {
                plo += __shfl_xor_sync(0xffffffffu, plo, off);
                phi += __shfl_xor_sync(0xffffffffu, phi, off);
                qlo += __shfl_xor_sync(0xffffffffu, qlo, off);
                qhi += __shfl_xor_sync(0xffffffffu, qhi, off);
            }
            if ((l & 3) == 0) {
                int rr = wr * 32 + mt * 16 + (l >> 2);
                Ses[rr * 2 + wc] = plo;
                Ses[(rr + 8) * 2 + wc] = phi;
                Sed[rr * 2 + wc] = qlo;
                Sed[(rr + 8) * 2 + wc] = qhi;
            }
        }
        __syncthreads();
        if (tid < 128) {
            int row = bm + tid;
            if (row < n) {
                g_es[row * 4 + head] = Ses[tid * 2] + Ses[tid * 2 + 1];
                g_ed[row * 4 + head] = Sed[tid * 2] + Sed[tid * 2 + 1];
            }
        }
    } else {
#pragma unroll
        for (int mt = 0; mt < 2; mt++) {
            int r0 = bm + wr * 32 + mt * 16 + (l >> 2);
            int r1 = r0 + 8;
#pragma unroll
            for (int nt = 0; nt < 4; nt++) {
                int col = bn + wc * 32 + nt * 8 + 2 * (l & 3);
                if (r0 < n) *(float2*)&Cf[(size_t)r0 * ncols + col] =
                    make_float2(c[mt][nt][0], c[mt][nt][1]);
                if (r1 < n) *(float2*)&Cf[(size_t)r1 * ncols + col] =
                    make_float2(c[mt][nt][2], c[mt][nt][3]);
            }
        }
    }
}

// ===== mega kernel 1: y<4 -> W1 GEMM head y (+attn); y==4 -> skip GEMM; =====
// ===== y==5 -> edge histogram (grid-stride). All mutually independent. ======
__global__ void __launch_bounds__(256) mega1_kernel(
    const float* __restrict__ x, const float* __restrict__ W1,
    const float* __restrict__ Wskip,
    const float* __restrict__ asrc, const float* __restrict__ adst,
    const int* __restrict__ ei, int n, int E, int etot)
{
    __shared__ __half As[128 * 72];
    __shared__ __half Bs[64 * 72];
    int y = blockIdx.y;
    if (y < 4) {
        gemm_body<true, true>(As, Bs, nullptr, x, W1, nullptr, g_h1h,
                              n, NFIN, NHC, y, blockIdx.x, asrc, adst);
    } else if (y == 4) {
        gemm_body<false, true>(As, Bs, nullptr, x, Wskip, g_skip, nullptr,
                               n, NFIN, NC, 0, blockIdx.x, nullptr, nullptr);
    } else {
        for (int e = blockIdx.x * blockDim.x + threadIdx.x; e < etot;
             e += gridDim.x * blockDim.x) {
            int d = (e < E) ? ei[E + e] : (e - E);
            atomicAdd(&g_cnt[d], 1);
        }
    }
}

// ===== layer-2 GEMM (fp16 A) =====
__global__ void __launch_bounds__(256) hgemm2_kernel(
    const __half* __restrict__ Ah, const float* __restrict__ Bf,
    int n, const float* __restrict__ asrc, const float* __restrict__ adst)
{
    __shared__ __half As[128 * 72];
    __shared__ __half Bs[64 * 72];
    gemm_body<true, false>(As, Bs, Ah, nullptr, Bf, nullptr, g_h1h,
                           n, NC, NHC, blockIdx.y, blockIdx.x, asrc, adst);
}

// == fused softmax + gather + BN-stats: warp per dst node, 4-wide pipeline ===
__global__ void __launch_bounds__(256) aggregate_kernel(
    int n, float* __restrict__ sums, float* __restrict__ sumsq)
{
    __shared__ float bsum[NC], bsq[NC];
    const int tid = threadIdx.x;
    if (tid < NC) { bsum[tid] = 0.f; bsq[tid] = 0.f; }
    __syncthreads();

    int w = (blockIdx.x * blockDim.x + tid) >> 5;
    int lane = tid & 31;
    const int h = lane >> 3;
    const int cb = (lane & 7) * 8;
    float a[8] = {0.f, 0.f, 0.f, 0.f, 0.f, 0.f, 0.f, 0.f};
    bool active = (w < n);

    if (active) {
        int beg = g_rowptr[w], end = g_rowptr[w + 1];
        float edv = g_ed[w * 4 + h];
        float s = 0.f;
        const __half* hb = g_h1h + h * 64 + cb;
        float a0 = 0.f, a1 = 0.f, a2 = 0.f, a3 = 0.f;
        float a4 = 0.f, a5 = 0.f, a6 = 0.f, a7 = 0.f;

        int pos = beg;
        for (; pos + 4 <= end; pos += 4) {
            int s0 = g_csrc[pos], s1 = g_csrc[pos + 1];
            int s2 = g_csrc[pos + 2], s3 = g_csrc[pos + 3];
            float e0 = g_es[s0 * 4 + h] + edv;
            float e1 = g_es[s1 * 4 + h] + edv;
            float e2 = g_es[s2 * 4 + h] + edv;
            float e3 = g_es[s3 * 4 + h] + edv;
            uint4 v0 = *(const uint4*)(hb + (size_t)s0 * NHC);
            uint4 v1 = *(const uint4*)(hb + (size_t)s1 * NHC);
            uint4 v2 = *(const uint4*)(hb + (size_t)s2 * NHC);
            uint4 v3 = *(const uint4*)(hb + (size_t)s3 * NHC);
            e0 = e0 > 0.f ? e0 : 0.2f * e0; float p0 = __expf(e0);
            e1 = e1 > 0.f ? e1 : 0.2f * e1; float p1 = __expf(e1);
            e2 = e2 > 0.f ? e2 : 0.2f * e2; float p2 = __expf(e2);
            e3 = e3 > 0.f ? e3 : 0.2f * e3; float p3 = __expf(e3);
            s += (p0 + p1) + (p2 + p3);
#define ACC(vv, pp) { \
            float2 f0 = __half22float2(*(__half2*)&vv.x); \
            float2 f1 = __half22float2(*(__half2*)&vv.y); \
            float2 f2 = __half22float2(*(__half2*)&vv.z); \
            float2 f3 = __half22float2(*(__half2*)&vv.w); \
            a0 += pp * f0.x; a1 += pp * f0.y; a2 += pp * f1.x; a3 += pp * f1.y; \
            a4 += pp * f2.x; a5 += pp * f2.y; a6 += pp * f3.x; a7 += pp * f3.y; }
            ACC(v0, p0) ACC(v1, p1) ACC(v2, p2) ACC(v3, p3)
        }
        for (; pos < end; pos++) {
            int s0 = g_csrc[pos];
            float e0 = g_es[s0 * 4 + h] + edv;
            uint4 v0 = *(const uint4*)(hb + (size_t)s0 * NHC);
            e0 = e0 > 0.f ? e0 : 0.2f * e0; float p0 = __expf(e0);
            s += p0;
            ACC(v0, p0)
        }
#undef ACC
        float inv = 0.25f / (s + 1e-16f);
        a[0] = a0 * inv; a[1] = a1 * inv; a[2] = a2 * inv; a[3] = a3 * inv;
        a[4] = a4 * inv; a[5] = a5 * inv; a[6] = a6 * inv; a[7] = a7 * inv;
    }
#pragma unroll
    for (int j = 0; j < 8; j++) {
        a[j] += __shfl_xor_sync(0xffffffffu, a[j], 8);
        a[j] += __shfl_xor_sync(0xffffffffu, a[j], 16);
    }
    if (active && lane < 8) {
        *(float4*)&g_acc[w * NC + lane * 8]     = make_float4(a[0], a[1], a[2], a[3]);
        *(float4*)&g_acc[w * NC + lane * 8 + 4] = make_float4(a[4], a[5], a[6], a[7]);
#pragma unroll
        for (int j = 0; j < 8; j++) {
            atomicAdd(&bsum[lane * 8 + j], a[j]);
            atomicAdd(&bsq[lane * 8 + j], a[j] * a[j]);
        }
    }
    __syncthreads();
    if (tid < NC) {
        atomicAdd(&sums[tid], bsum[tid]);
        atomicAdd(&sumsq[tid], bsq[tid]);
    }
}

// ===== fused epilogue 1: BN finalize inline; h = gelu(BN + skip + bskip) ====
// GAT bias b1/b2 cancels inside BatchNorm (additive constant) -> never applied.
__global__ void fuse1_kernel(const float* __restrict__ bskip,
                             const float* __restrict__ gamma,
                             const float* __restrict__ beta,
                             const float* __restrict__ sums,
                             const float* __restrict__ sumsq,
                             float ninv, int total)
{
    int i = blockIdx.x * blockDim.x + threadIdx.x;
    if (i >= total) return;
    int c = i & 63;
    float mu = sums[c] * ninv;
    float var = sumsq[c] * ninv - mu * mu;
    float sc = gamma[c] * rsqrtf(var + BN_EPS);
    float sh = beta[c] - mu * sc;
    float x = g_acc[i] * sc + sh + g_skip[i] + bskip[c];
    float y = gelu_exact(x);
    g_hmid[i] = y;
    g_hmidh[i] = __float2half_rn(y);
}

// ======= fused epilogue 2 + pool: block per graph, BN finalize inline =======
__device__ __forceinline__ int lower_bound_dev(const int* arr, int n, int target) {
    int lo = 0, hi = n;
    while (lo < hi) {
        int mid = (lo + hi) >> 1;
        if (arr[mid] < target) lo = mid + 1; else hi = mid;
    }
    return lo;
}

__global__ void fuse2_pool_kernel(const int* __restrict__ batch,
                                  const float* __restrict__ gamma,
                                  const float* __restrict__ beta,
                                  const float* __restrict__ sums,
                                  const float* __restrict__ sumsq,
                                  float ninv,
                                  float* __restrict__ out, int n)
{
    int g = blockIdx.x;
    __shared__ int bounds[2];
    if (threadIdx.x < 2)
        bounds[threadIdx.x] = lower_bound_dev(batch, n, g + threadIdx.x);
    __syncthreads();
    int lo = bounds[0], hi = bounds[1];
    int c = threadIdx.x & 63, rq = threadIdx.x >> 6;
    float mu = sums[c] * ninv;
    float var = sumsq[c] * ninv - mu * mu;
    float sc = gamma[c] * rsqrtf(var + BN_EPS);
    float sh = beta[c] - mu * sc;
    float s = 0.f;
    for (int node = lo + rq; node < hi; node += 4) {
        float x = g_acc[node * NC + c] * sc + sh + g_hmid[node * NC + c];
        s += gelu_exact(x);
    }
    __shared__ float red[256];
    red[threadIdx.x] = s;
    __syncthreads();
    if (threadIdx.x < 64) {
        float tot = red[c] + red[c + 64] + red[c + 128] + red[c + 192];
        out[g * NC + c] = tot / fmaxf((float)(hi - lo), 1.f);
    }
}

// ================= launch =================
extern "C" void kernel_launch(void* const* d_in, const int* in_sizes, int n_in,
                              void* d_out, int out_size) {
    const float* x      = (const float*)d_in[0];
    const float* W1     = (const float*)d_in[1];
    const float* a_src1 = (const float*)d_in[2];
    const float* a_dst1 = (const float*)d_in[3];
    const float* Wskip  = (const float*)d_in[5];
    const float* bskip  = (const float*)d_in[6];
    const float* g1     = (const float*)d_in[7];
    const float* be1    = (const float*)d_in[8];
    const float* W2     = (const float*)d_in[9];
    const float* a_src2 = (const float*)d_in[10];
    const float* a_dst2 = (const float*)d_in[11];
    const float* g2     = (const float*)d_in[13];
    const float* be2    = (const float*)d_in[14];
    const int*   ei     = (const int*)d_in[15];
    const int*   batch  = (const int*)d_in[16];
    float* out = (float*)d_out;

    int n = in_sizes[0] / NFIN;
    int E = in_sizes[15] / 2;
    int etot = E + n;
    float ninv = 1.f / (float)n;

    __half* p_hmidh;
    float* p_stats;
    cudaGetSymbolAddress((void**)&p_hmidh, g_hmidh);
    cudaGetSymbolAddress((void**)&p_stats, g_bnstats);
    float* p_sums0  = p_stats;
    float* p_sumsq0 = p_stats + NC;
    float* p_sums1  = p_stats + 2 * NC;
    float* p_sumsq1 = p_stats + 3 * NC;

    int eb = (etot + 255) / 256;
    int gx = (n + 127) / 128;
    int fb = (n * NC + 255) / 256;
    int ab = (n * 32 + 255) / 256;

    // zero counts + stats
    zero_cnt_kernel<<<(n + 255) / 256, 256>>>(n);

    // mega kernel: W1 GEMM (4 heads, attn) || skip GEMM || edge histogram
    mega1_kernel<<<dim3(gx, 6), 256>>>(x, W1, Wskip, a_src1, a_dst1, ei, n, E, etot);

    // CSR finish
    scan_kernel<<<1, 1024>>>(n);
    scatter_kernel<<<eb, 256>>>(ei, E, etot);

    // layer 1 aggregate + epilogue
    aggregate_kernel<<<ab, 256>>>(n, p_sums0, p_sumsq0);
    fuse1_kernel<<<fb, 256>>>(bskip, g1, be1, p_sums0, p_sumsq0, ninv, n * NC);

    // layer 2
    hgemm2_kernel<<<dim3(gx, 4), 256>>>(p_hmidh, W2, n, a_src2, a_dst2);
    aggregate_kernel<<<ab, 256>>>(n, p_sums1, p_sumsq1);
    fuse2_pool_kernel<<<N_GRAPH, 256>>>(batch, g2, be2, p_sums1, p_sumsq1, ninv, out, n);
}